// round 4
// baseline (speedup 1.0000x reference)
#include <cuda_runtime.h>
#include <math.h>
#include <stdint.h>

#define SEQ   512
#define HID   512
#define IN0   1088
#define IN1   1024
#define GATES 2048
#define MLPH  100
#define PAIRD 2048
#define RCTAS 64   // CTAs per LSTM direction

// ---------------- device scratch (no allocations allowed) ----------------
__device__ float g_x0[SEQ * IN0];            // embeddings concat
__device__ float g_xw0[SEQ * GATES];         // xw fwd (current layer)
__device__ float g_xw1[SEQ * GATES];         // xw bwd (current layer)
__device__ float g_h0[SEQ * 2 * HID];        // layer0 output [t][fwd|bwd]
__device__ float g_h1[SEQ * 2 * HID];        // layer1 output
__device__ float g_sh[SEQ * MLPH];
__device__ float g_sm[SEQ * MLPH];
__device__ float g_scores[SEQ * SEQ];
__device__ unsigned g_cnt[2];                // per-direction exit counters (zero-init)
__device__ unsigned g_flags[2][64];          // per-direction per-CTA step flags (zero-init)

// ---------------- helpers ----------------
__device__ __forceinline__ unsigned ld_acq(const unsigned* p) {
    unsigned v;
    asm volatile("ld.acquire.gpu.u32 %0, [%1];" : "=r"(v) : "l"(p) : "memory");
    return v;
}
__device__ __forceinline__ void st_rel(unsigned* p, unsigned v) {
    asm volatile("st.relaxed.gpu.u32 [%0], %1;" :: "l"(p), "r"(v) : "memory");
}
__device__ __forceinline__ float fsig(float x) {               // fast sigmoid, err ~1e-7
    return __fdividef(1.0f, 1.0f + __expf(-x));
}
__device__ __forceinline__ float ftanh_acc(float x) {          // fast tanh, err ~1e-7
    return 1.0f - __fdividef(2.0f, __expf(2.0f * x) + 1.0f);
}
__device__ __forceinline__ float tanhap(float x) {             // HW tanh, err ~6e-4
    float y;
    asm("tanh.approx.f32 %0, %1;" : "=f"(y) : "f"(x));
    return y;
}

// ---------------- embeddings ----------------
__global__ void embed_kernel(const int* __restrict__ wi, const int* __restrict__ pi,
                             const float* __restrict__ we, const float* __restrict__ pe) {
    int t = blockIdx.x;
    int w = wi[t], p = pi[t];
    const float* wr = we + (size_t)w * 1024;
    const float* pr = pe + (size_t)p * 64;
    float* out = g_x0 + (size_t)t * IN0;
    for (int i = threadIdx.x; i < 1024; i += blockDim.x) out[i] = wr[i];
    for (int i = threadIdx.x; i < 64; i += blockDim.x) out[1024 + i] = pr[i];
}

// ---------------- generic tiled GEMM: C[M,N] = A[M,K] * B[N,K]^T (+bias) ----------------
__global__ void gemm_nt(const float* __restrict__ A, int lda,
                        const float* __restrict__ B, int ldb,
                        const float* __restrict__ bias,
                        float* __restrict__ C, int ldc,
                        int M, int N, int K) {
    __shared__ __align__(16) float As[16][68];
    __shared__ __align__(16) float Bs[16][68];
    int bm = blockIdx.y * 64, bn = blockIdx.x * 64;
    int tid = threadIdx.x;
    int tx = tid & 15, ty = tid >> 4;
    int lr = tid >> 2;          // 0..63: row within tile
    int lk = (tid & 3) * 4;     // k offset within 16

    float acc[4][4];
#pragma unroll
    for (int i = 0; i < 4; i++)
#pragma unroll
        for (int j = 0; j < 4; j++) acc[i][j] = 0.f;

    for (int k0 = 0; k0 < K; k0 += 16) {
        {
            int row = bm + lr;
            float4 v = make_float4(0.f, 0.f, 0.f, 0.f);
            if (row < M) v = *(const float4*)(A + (size_t)row * lda + k0 + lk);
            As[lk + 0][lr] = v.x; As[lk + 1][lr] = v.y; As[lk + 2][lr] = v.z; As[lk + 3][lr] = v.w;
            int rowb = bn + lr;
            float4 u = make_float4(0.f, 0.f, 0.f, 0.f);
            if (rowb < N) u = *(const float4*)(B + (size_t)rowb * ldb + k0 + lk);
            Bs[lk + 0][lr] = u.x; Bs[lk + 1][lr] = u.y; Bs[lk + 2][lr] = u.z; Bs[lk + 3][lr] = u.w;
        }
        __syncthreads();
#pragma unroll
        for (int k = 0; k < 16; k++) {
            float4 a4 = *(const float4*)&As[k][ty * 4];
            float4 b4 = *(const float4*)&Bs[k][tx * 4];
            float a[4] = {a4.x, a4.y, a4.z, a4.w};
            float b[4] = {b4.x, b4.y, b4.z, b4.w};
#pragma unroll
            for (int i = 0; i < 4; i++)
#pragma unroll
                for (int j = 0; j < 4; j++) acc[i][j] = fmaf(a[i], b[j], acc[i][j]);
        }
        __syncthreads();
    }
#pragma unroll
    for (int i = 0; i < 4; i++) {
        int r = bm + ty * 4 + i;
        if (r >= M) continue;
#pragma unroll
        for (int j = 0; j < 4; j++) {
            int c = bn + tx * 4 + j;
            if (c < N) C[(size_t)r * ldc + c] = acc[i][j] + (bias ? bias[c] : 0.f);
        }
    }
}

// ---------------- LSTM layer recurrence (both directions, distributed flag barrier) ------
// grid = 128 CTAs (64 fwd, 64 bwd), 256 threads. CTA owns 8 h-indices (32 gate rows).
// Dynamic smem: sW[32][513] + sh[512] + zp[32*9]
__global__ void lstm_layer(const float* __restrict__ whh_f, const float* __restrict__ whh_b,
                           const float* __restrict__ xw_f, const float* __restrict__ xw_b,
                           float* __restrict__ hout) {
    extern __shared__ float smem[];
    float* sW = smem;                  // 32 * 513
    float* sh = smem + 32 * 513;       // 512
    float* zp = sh + 512;              // 32 * 9

    int dir = blockIdx.x >> 6;
    int j = blockIdx.x & 63;
    int hbase = j * 8;
    const float* W = dir ? whh_b : whh_f;
    const float* xw = dir ? xw_b : xw_f;
    int tid = threadIdx.x;
    unsigned* flags = g_flags[dir];

    // load this CTA's 32 W_hh rows into smem (row rr = g*8+k -> global row g*512+hbase+k)
    {
        int rr = tid >> 3, part = tid & 7;
        int g = rr >> 3, k = rr & 7;
        const float* src = W + (size_t)(g * 512 + hbase + k) * 512 + part * 64;
        float* dst = sW + rr * 513 + part * 64;
#pragma unroll
        for (int i = 0; i < 64; i += 4) {
            float4 v = *(const float4*)(src + i);
            dst[i] = v.x; dst[i + 1] = v.y; dst[i + 2] = v.z; dst[i + 3] = v.w;
        }
    }

    float c_state = 0.f;           // owned by threads 0..7
    int row = tid & 31;            // gate row within CTA
    int ck = tid >> 5;             // K chunk 0..7
    const int base = ck * 64;

    for (int t = 0; t < 512; t++) {
        int pos = dir ? (511 - t) : t;

        // prefetch gate inputs (independent of h) — overlaps the flag poll below
        float xg0 = 0.f, xg1 = 0.f, xg2 = 0.f, xg3 = 0.f;
        if (tid < 8) {
            const float* xr = xw + (size_t)pos * GATES + hbase + tid;
            xg0 = __ldg(xr);
            xg1 = __ldg(xr + 512);
            xg2 = __ldg(xr + 1024);
            xg3 = __ldg(xr + 1536);
        }

        // gather h_prev: thread k waits for producer k's flag, pulls its 8 h values
        if (t == 0) {
            sh[tid] = 0.f; sh[tid + 256] = 0.f;
        } else if (tid < 64) {
            unsigned tu = (unsigned)t;
            const unsigned* fl = &flags[tid];
            while (ld_acq(fl) < tu) { }
            int ppos = dir ? (pos + 1) : (t - 1);
            const float* hp = hout + (size_t)ppos * 1024 + (dir << 9) + (tid << 3);
            float4 a = __ldcg((const float4*)hp);
            float4 b = __ldcg((const float4*)(hp + 4));
            float* d = sh + (tid << 3);
            *(float4*)d = a;
            *(float4*)(d + 4) = b;
        }
        __syncthreads();

        // matvec partial: row dot over chunk ck (64 elems), 4-way ILP
        {
            const float* wrow = sW + row * 513 + base;
            const float* hv = sh + base;
            float a0 = 0.f, a1 = 0.f, a2 = 0.f, a3 = 0.f;
#pragma unroll
            for (int i = 0; i < 64; i += 4) {
                a0 = fmaf(wrow[i + 0], hv[i + 0], a0);
                a1 = fmaf(wrow[i + 1], hv[i + 1], a1);
                a2 = fmaf(wrow[i + 2], hv[i + 2], a2);
                a3 = fmaf(wrow[i + 3], hv[i + 3], a3);
            }
            zp[row * 9 + ck] = (a0 + a1) + (a2 + a3);
        }
        __syncthreads();

        // gates & state update by threads 0..7 (thread k handles h index hbase+k)
        if (tid < 8) {
            float z0 = xg0, z1 = xg1, z2 = xg2, z3 = xg3;
#pragma unroll
            for (int c = 0; c < 8; c++) {
                z0 += zp[(tid) * 9 + c];
                z1 += zp[(8 + tid) * 9 + c];
                z2 += zp[(16 + tid) * 9 + c];
                z3 += zp[(24 + tid) * 9 + c];
            }
            float gi = fsig(z0);
            float gf = fsig(z1);
            float gg = ftanh_acc(z2);
            float go = fsig(z3);
            c_state = gf * c_state + gi * gg;
            float h = go * ftanh_acc(c_state);
            __stcg(hout + (size_t)pos * 1024 + (dir << 9) + hbase + tid, h);
            __syncwarp(0xFF);
            if (tid == 0) {
                __threadfence();
                st_rel(&flags[j], (unsigned)(t + 1));
            }
        }
        // no trailing block sync needed: next sh writes are fenced by the flag-poll +
        // the post-matvec __syncthreads of this iteration; zp next write is after sync #1.
    }

    // exit protocol: count arrivals; CTA j==0 (per dir) resets flags + counter for replay
    if (tid == 0) {
        __threadfence();
        atomicAdd(&g_cnt[dir], 1u);
        if (j == 0) {
            while (ld_acq(&g_cnt[dir]) < (unsigned)RCTAS) { }
            for (int k = 0; k < 64; k++) flags[k] = 0;
            __threadfence();
            atomicExch(&g_cnt[dir], 0u);
        }
    }
}

// ---------------- pairwise MLP edge scores ----------------
// scores[h][m] = sum_j tanh(sh[h][j] + sm[m][j] + b1[j]) * W2[j] + b2
__global__ void pair_score(const float* __restrict__ b1, const float* __restrict__ W2,
                           const float* __restrict__ b2) {
    __shared__ float Sh[32][101];
    __shared__ float Sm[32][101];
    __shared__ float sb1[MLPH], sw2[MLPH];
    int bh = blockIdx.y * 32, bm = blockIdx.x * 32;
    int tid = threadIdx.x;
    for (int i = tid; i < 32 * MLPH; i += 256) {
        int r = i / MLPH, c = i % MLPH;
        Sh[r][c] = g_sh[(size_t)(bh + r) * MLPH + c];
        Sm[r][c] = g_sm[(size_t)(bm + r) * MLPH + c];
    }
    if (tid < MLPH) { sb1[tid] = b1[tid]; sw2[tid] = W2[tid]; }
    __syncthreads();

    int tx = tid & 15, ty = tid >> 4;
    int h0 = ty * 2, m0 = tx * 2;
    float acc00 = 0.f, acc01 = 0.f, acc10 = 0.f, acc11 = 0.f;
    for (int jx = 0; jx < MLPH; jx++) {
        float w = sw2[jx], bb = sb1[jx];
        float a0 = Sh[h0][jx] + bb;
        float a1 = Sh[h0 + 1][jx] + bb;
        float c0 = Sm[m0][jx];
        float c1 = Sm[m0 + 1][jx];
        acc00 = fmaf(tanhap(a0 + c0), w, acc00);
        acc01 = fmaf(tanhap(a0 + c1), w, acc01);
        acc10 = fmaf(tanhap(a1 + c0), w, acc10);
        acc11 = fmaf(tanhap(a1 + c1), w, acc11);
    }
    float b2v = __ldg(b2);
    g_scores[(size_t)(bh + h0) * SEQ + bm + m0]         = acc00 + b2v;
    g_scores[(size_t)(bh + h0) * SEQ + bm + m0 + 1]     = acc01 + b2v;
    g_scores[(size_t)(bh + h0 + 1) * SEQ + bm + m0]     = acc10 + b2v;
    g_scores[(size_t)(bh + h0 + 1) * SEQ + bm + m0 + 1] = acc11 + b2v;
}

// ---------------- softmax over axis 0 (over h, per column m) ----------------
__global__ void softmax0(float* __restrict__ out) {
    int m = blockIdx.x;
    int tid = threadIdx.x;  // 128
    float v[4];
#pragma unroll
    for (int i = 0; i < 4; i++) v[i] = g_scores[(size_t)(tid + 128 * i) * SEQ + m];
    float mx = fmaxf(fmaxf(v[0], v[1]), fmaxf(v[2], v[3]));
    __shared__ float red[128];
    red[tid] = mx; __syncthreads();
    for (int o = 64; o > 0; o >>= 1) {
        if (tid < o) red[tid] = fmaxf(red[tid], red[tid + o]);
        __syncthreads();
    }
    mx = red[0]; __syncthreads();
    float e[4]; float ssum = 0.f;
#pragma unroll
    for (int i = 0; i < 4; i++) { e[i] = __expf(v[i] - mx); ssum += e[i]; }
    red[tid] = ssum; __syncthreads();
    for (int o = 64; o > 0; o >>= 1) {
        if (tid < o) red[tid] += red[tid + o];
        __syncthreads();
    }
    float inv = 1.f / red[0];
#pragma unroll
    for (int i = 0; i < 4; i++) out[(size_t)(tid + 128 * i) * SEQ + m] = e[i] * inv;
}

// ---------------- launch ----------------
extern "C" void kernel_launch(void* const* d_in, const int* in_sizes, int n_in,
                              void* d_out, int out_size) {
    const int*   wi  = (const int*)d_in[0];
    const int*   pi  = (const int*)d_in[1];
    const float* we  = (const float*)d_in[2];
    const float* pe  = (const float*)d_in[3];
    const float* wih0f = (const float*)d_in[4];
    const float* whh0f = (const float*)d_in[5];
    const float* b0f   = (const float*)d_in[6];
    const float* wih0b = (const float*)d_in[7];
    const float* whh0b = (const float*)d_in[8];
    const float* b0b   = (const float*)d_in[9];
    const float* wih1f = (const float*)d_in[10];
    const float* whh1f = (const float*)d_in[11];
    const float* b1f   = (const float*)d_in[12];
    const float* wih1b = (const float*)d_in[13];
    const float* whh1b = (const float*)d_in[14];
    const float* b1b   = (const float*)d_in[15];
    const float* W1    = (const float*)d_in[16];
    const float* b1    = (const float*)d_in[17];
    const float* W2    = (const float*)d_in[18];
    const float* b2    = (const float*)d_in[19];
    float* out = (float*)d_out;

    float *p_x0, *p_xw0, *p_xw1, *p_h0, *p_h1, *p_sh, *p_sm;
    cudaGetSymbolAddress((void**)&p_x0, g_x0);
    cudaGetSymbolAddress((void**)&p_xw0, g_xw0);
    cudaGetSymbolAddress((void**)&p_xw1, g_xw1);
    cudaGetSymbolAddress((void**)&p_h0, g_h0);
    cudaGetSymbolAddress((void**)&p_h1, g_h1);
    cudaGetSymbolAddress((void**)&p_sh, g_sh);
    cudaGetSymbolAddress((void**)&p_sm, g_sm);

    const int lstm_smem = (32 * 513 + 512 + 32 * 9) * (int)sizeof(float);
    cudaFuncSetAttribute(lstm_layer, cudaFuncAttributeMaxDynamicSharedMemorySize, lstm_smem);

    // 1. embeddings
    embed_kernel<<<SEQ, 256>>>(wi, pi, we, pe);

    // 2. layer0 input GEMMs: xw = x0 @ w_ih^T + b
    {
        dim3 grid(GATES / 64, SEQ / 64);
        gemm_nt<<<grid, 256>>>(p_x0, IN0, wih0f, IN0, b0f, p_xw0, GATES, SEQ, GATES, IN0);
        gemm_nt<<<grid, 256>>>(p_x0, IN0, wih0b, IN0, b0b, p_xw1, GATES, SEQ, GATES, IN0);
    }

    // 3. layer0 recurrence
    lstm_layer<<<2 * RCTAS, 256, lstm_smem>>>(whh0f, whh0b, p_xw0, p_xw1, p_h0);

    // 4. layer1 input GEMMs
    {
        dim3 grid(GATES / 64, SEQ / 64);
        gemm_nt<<<grid, 256>>>(p_h0, IN1, wih1f, IN1, b1f, p_xw0, GATES, SEQ, GATES, IN1);
        gemm_nt<<<grid, 256>>>(p_h0, IN1, wih1b, IN1, b1b, p_xw1, GATES, SEQ, GATES, IN1);
    }

    // 5. layer1 recurrence
    lstm_layer<<<2 * RCTAS, 256, lstm_smem>>>(whh1f, whh1b, p_xw0, p_xw1, p_h1);

    // 6. MLP projections (W1 is [100, 2048] -> ldb = PAIRD)
    {
        dim3 grid((MLPH + 63) / 64, SEQ / 64);
        gemm_nt<<<grid, 256>>>(p_h1, 2 * HID, W1, PAIRD, nullptr, p_sh, MLPH, SEQ, MLPH, 2 * HID);
        gemm_nt<<<grid, 256>>>(p_h1, 2 * HID, W1 + 1024, PAIRD, nullptr, p_sm, MLPH, SEQ, MLPH, 2 * HID);
    }

    // 7. pairwise scores
    {
        dim3 grid(SEQ / 32, SEQ / 32);
        pair_score<<<grid, 256>>>(b1, W2, b2);
    }

    // 8. softmax over heads (axis 0)
    softmax0<<<SEQ, 128>>>(out);
}

// round 5
// speedup vs baseline: 1.3827x; 1.3827x over previous
#include <cuda_runtime.h>
#include <math.h>
#include <stdint.h>

#define SEQ   512
#define HID   512
#define IN0   1088
#define IN1   1024
#define GATES 2048
#define MLPH  100
#define PAIRD 2048
#define RCTAS 64   // CTAs per LSTM direction

// ---------------- device scratch (no allocations allowed) ----------------
__device__ float g_x0[SEQ * IN0];
__device__ float g_xw0[SEQ * GATES];
__device__ float g_xw1[SEQ * GATES];
__device__ float g_h0[SEQ * 2 * HID];
__device__ float g_h1[SEQ * 2 * HID];
__device__ float g_sh[SEQ * MLPH];
__device__ float g_sm[SEQ * MLPH];
__device__ float g_scores[SEQ * SEQ];
__device__ unsigned g_grp[2][8];      // group counters (monotonic, zero-init)
__device__ unsigned g_root[2];        // root counters (monotonic)
__device__ unsigned g_go[2][32];      // go word per direction, padded to own 128B line
__device__ unsigned g_cnt[2];         // exit counters

// ---------------- helpers ----------------
__device__ __forceinline__ unsigned ld_acq(const unsigned* p) {
    unsigned v;
    asm volatile("ld.acquire.gpu.u32 %0, [%1];" : "=r"(v) : "l"(p) : "memory");
    return v;
}
__device__ __forceinline__ void st_rel(unsigned* p, unsigned v) {
    asm volatile("st.relaxed.gpu.u32 [%0], %1;" :: "l"(p), "r"(v) : "memory");
}
__device__ __forceinline__ float fsig(float x) {               // err ~1e-7
    return __fdividef(1.0f, 1.0f + __expf(-x));
}
__device__ __forceinline__ float ftanh_acc(float x) {          // err ~1e-7
    return 1.0f - __fdividef(2.0f, __expf(2.0f * x) + 1.0f);
}
__device__ __forceinline__ float tanhap(float x) {             // HW tanh, err ~6e-4
    float y;
    asm("tanh.approx.f32 %0, %1;" : "=f"(y) : "f"(x));
    return y;
}

// ---------------- embeddings ----------------
__global__ void embed_kernel(const int* __restrict__ wi, const int* __restrict__ pi,
                             const float* __restrict__ we, const float* __restrict__ pe) {
    int t = blockIdx.x;
    int w = wi[t], p = pi[t];
    const float* wr = we + (size_t)w * 1024;
    const float* pr = pe + (size_t)p * 64;
    float* out = g_x0 + (size_t)t * IN0;
    for (int i = threadIdx.x; i < 1024; i += blockDim.x) out[i] = wr[i];
    for (int i = threadIdx.x; i < 64; i += blockDim.x) out[1024 + i] = pr[i];
}

// ---------------- generic tiled GEMM: C[M,N] = A[M,K] * B[N,K]^T (+bias) ----------------
__global__ void gemm_nt(const float* __restrict__ A, int lda,
                        const float* __restrict__ B, int ldb,
                        const float* __restrict__ bias,
                        float* __restrict__ C, int ldc,
                        int M, int N, int K) {
    __shared__ __align__(16) float As[16][68];
    __shared__ __align__(16) float Bs[16][68];
    int bm = blockIdx.y * 64, bn = blockIdx.x * 64;
    int tid = threadIdx.x;
    int tx = tid & 15, ty = tid >> 4;
    int lr = tid >> 2;
    int lk = (tid & 3) * 4;

    float acc[4][4];
#pragma unroll
    for (int i = 0; i < 4; i++)
#pragma unroll
        for (int j = 0; j < 4; j++) acc[i][j] = 0.f;

    for (int k0 = 0; k0 < K; k0 += 16) {
        {
            int row = bm + lr;
            float4 v = make_float4(0.f, 0.f, 0.f, 0.f);
            if (row < M) v = *(const float4*)(A + (size_t)row * lda + k0 + lk);
            As[lk + 0][lr] = v.x; As[lk + 1][lr] = v.y; As[lk + 2][lr] = v.z; As[lk + 3][lr] = v.w;
            int rowb = bn + lr;
            float4 u = make_float4(0.f, 0.f, 0.f, 0.f);
            if (rowb < N) u = *(const float4*)(B + (size_t)rowb * ldb + k0 + lk);
            Bs[lk + 0][lr] = u.x; Bs[lk + 1][lr] = u.y; Bs[lk + 2][lr] = u.z; Bs[lk + 3][lr] = u.w;
        }
        __syncthreads();
#pragma unroll
        for (int k = 0; k < 16; k++) {
            float4 a4 = *(const float4*)&As[k][ty * 4];
            float4 b4 = *(const float4*)&Bs[k][tx * 4];
            float a[4] = {a4.x, a4.y, a4.z, a4.w};
            float b[4] = {b4.x, b4.y, b4.z, b4.w};
#pragma unroll
            for (int i = 0; i < 4; i++)
#pragma unroll
                for (int j = 0; j < 4; j++) acc[i][j] = fmaf(a[i], b[j], acc[i][j]);
        }
        __syncthreads();
    }
#pragma unroll
    for (int i = 0; i < 4; i++) {
        int r = bm + ty * 4 + i;
        if (r >= M) continue;
#pragma unroll
        for (int j = 0; j < 4; j++) {
            int c = bn + tx * 4 + j;
            if (c < N) C[(size_t)r * ldc + c] = acc[i][j] + (bias ? bias[c] : 0.f);
        }
    }
}

// ---------------- LSTM recurrence: register weights + tree barrier + go-word ----------------
// grid = 128 CTAs (64 fwd, 64 bwd), 256 threads. CTA owns 8 h-indices (32 gate rows).
// Thread (row=tid&31, ck=tid>>5) holds 64 weights in registers.
__global__ void __launch_bounds__(256, 1)
lstm_layer(const float* __restrict__ whh_f, const float* __restrict__ whh_b,
           const float* __restrict__ xw_f, const float* __restrict__ xw_b,
           float* __restrict__ hout) {
    __shared__ float sh[512];
    __shared__ float zp[32 * 9];
    __shared__ float sact[32];

    int dir = blockIdx.x >> 6;
    int j = blockIdx.x & 63;
    int hbase = j * 8;
    const float* W = dir ? whh_b : whh_f;
    const float* xw = dir ? xw_b : xw_f;
    int tid = threadIdx.x;

    int row = tid & 31;            // gate row within CTA (0..31)
    int ck = tid >> 5;             // K chunk (0..7)
    const int base = ck * 64;

    // load this thread's 64 weights into registers:
    // global gate row = (row>>3)*512 + hbase + (row&7), cols [ck*64, ck*64+64)
    float w[64];
    {
        const float* src = W + (size_t)((row >> 3) * 512 + hbase + (row & 7)) * 512 + base;
#pragma unroll
        for (int i = 0; i < 64; i += 4) {
            float4 v = *(const float4*)(src + i);
            w[i] = v.x; w[i + 1] = v.y; w[i + 2] = v.z; w[i + 3] = v.w;
        }
    }

    unsigned* grp = &g_grp[dir][j >> 3];
    unsigned* root = &g_root[dir];
    unsigned* go = &g_go[dir][0];

    float c_state = 0.f;           // owned by threads 0..7

    for (int t = 0; t < 512; t++) {
        int pos = dir ? (511 - t) : t;

        // prefetch gate inputs (independent of h) — overlaps the spin below
        float xg = 0.f;
        if (tid < 32) {
            // thread (k=tid&7, g=tid>>3) fetches xw for gate g, h-index hbase+k
            const float* xr = xw + (size_t)pos * GATES + (tid >> 3) * 512 + hbase + (tid & 7);
            xg = __ldg(xr);
        }

        if (t == 0) {
            sh[tid] = 0.f; sh[tid + 256] = 0.f;
        } else if (tid == 0) {
            unsigned tu = (unsigned)t;
            while (ld_acq(go) < tu) { }
        }
        __syncthreads();   // (A) go observed -> whole CTA

        if (t > 0 && tid < 64) {
            int ppos = dir ? (pos + 1) : (t - 1);
            const float* hp = hout + (size_t)ppos * 1024 + (dir << 9) + (tid << 3);
            float4 a = __ldcg((const float4*)hp);
            float4 b = __ldcg((const float4*)(hp + 4));
            float* d = sh + (tid << 3);
            *(float4*)d = a;
            *(float4*)(d + 4) = b;
        }
        __syncthreads();   // (B) sh ready

        // matvec partial: register weights x broadcast smem h
        {
            const float* hv = sh + base;
            float a0 = 0.f, a1 = 0.f, a2 = 0.f, a3 = 0.f;
#pragma unroll
            for (int i = 0; i < 64; i += 4) {
                float4 h4 = *(const float4*)(hv + i);
                a0 = fmaf(w[i + 0], h4.x, a0);
                a1 = fmaf(w[i + 1], h4.y, a1);
                a2 = fmaf(w[i + 2], h4.z, a2);
                a3 = fmaf(w[i + 3], h4.w, a3);
            }
            zp[row * 9 + ck] = (a0 + a1) + (a2 + a3);
        }
        __syncthreads();   // (C) zp ready

        // 32 threads: per-gate-row sum + activation
        if (tid < 32) {
            int rr = (tid >> 3) * 8 + (tid & 7);   // == tid, kept for clarity
            const float* zr = zp + rr * 9;
            float z = xg;
#pragma unroll
            for (int c = 0; c < 8; c++) z += zr[c];
            int g = tid >> 3;
            sact[rr] = (g == 2) ? ftanh_acc(z) : fsig(z);
        }
        __syncwarp();      // warp 0 holds all 32 producers + the 8 state owners

        // 8 threads: state update + h store + arrival
        if (tid < 8) {
            float gi = sact[tid];
            float gf = sact[8 + tid];
            float gg = sact[16 + tid];
            float go_ = sact[24 + tid];
            c_state = gf * c_state + gi * gg;
            float h = go_ * ftanh_acc(c_state);
            __stcg(hout + (size_t)pos * 1024 + (dir << 9) + hbase + tid, h);
        }
        __syncwarp();
        if (tid == 0) {
            __threadfence();
            unsigned o = atomicAdd(grp, 1u);
            if ((o & 7) == 7) {                    // last of this 8-CTA group this step
                unsigned r = atomicAdd(root, 1u);
                if ((r & 7) == 7) {                // last group overall this step
                    __threadfence();
                    st_rel(go, (unsigned)(t + 1));
                }
            }
        }
    }

    // exit protocol: CTA j==0 per direction resets counters for the next launch/replay
    __syncthreads();
    if (tid == 0) {
        __threadfence();
        atomicAdd(&g_cnt[dir], 1u);
        if (j == 0) {
            while (ld_acq(&g_cnt[dir]) < (unsigned)RCTAS) { }
#pragma unroll
            for (int k = 0; k < 8; k++) g_grp[dir][k] = 0;
            g_root[dir] = 0;
            g_go[dir][0] = 0;
            __threadfence();
            atomicExch(&g_cnt[dir], 0u);
        }
    }
}

// ---------------- pairwise MLP edge scores ----------------
__global__ void pair_score(const float* __restrict__ b1, const float* __restrict__ W2,
                           const float* __restrict__ b2) {
    __shared__ float Sh[32][101];
    __shared__ float Sm[32][101];
    __shared__ float sb1[MLPH], sw2[MLPH];
    int bh = blockIdx.y * 32, bm = blockIdx.x * 32;
    int tid = threadIdx.x;
    for (int i = tid; i < 32 * MLPH; i += 256) {
        int r = i / MLPH, c = i % MLPH;
        Sh[r][c] = g_sh[(size_t)(bh + r) * MLPH + c];
        Sm[r][c] = g_sm[(size_t)(bm + r) * MLPH + c];
    }
    if (tid < MLPH) { sb1[tid] = b1[tid]; sw2[tid] = W2[tid]; }
    __syncthreads();

    int tx = tid & 15, ty = tid >> 4;
    int h0 = ty * 2, m0 = tx * 2;
    float acc00 = 0.f, acc01 = 0.f, acc10 = 0.f, acc11 = 0.f;
    for (int jx = 0; jx < MLPH; jx++) {
        float w = sw2[jx], bb = sb1[jx];
        float a0 = Sh[h0][jx] + bb;
        float a1 = Sh[h0 + 1][jx] + bb;
        float c0 = Sm[m0][jx];
        float c1 = Sm[m0 + 1][jx];
        acc00 = fmaf(tanhap(a0 + c0), w, acc00);
        acc01 = fmaf(tanhap(a0 + c1), w, acc01);
        acc10 = fmaf(tanhap(a1 + c0), w, acc10);
        acc11 = fmaf(tanhap(a1 + c1), w, acc11);
    }
    float b2v = __ldg(b2);
    g_scores[(size_t)(bh + h0) * SEQ + bm + m0]         = acc00 + b2v;
    g_scores[(size_t)(bh + h0) * SEQ + bm + m0 + 1]     = acc01 + b2v;
    g_scores[(size_t)(bh + h0 + 1) * SEQ + bm + m0]     = acc10 + b2v;
    g_scores[(size_t)(bh + h0 + 1) * SEQ + bm + m0 + 1] = acc11 + b2v;
}

// ---------------- softmax over axis 0 ----------------
__global__ void softmax0(float* __restrict__ out) {
    int m = blockIdx.x;
    int tid = threadIdx.x;  // 128
    float v[4];
#pragma unroll
    for (int i = 0; i < 4; i++) v[i] = g_scores[(size_t)(tid + 128 * i) * SEQ + m];
    float mx = fmaxf(fmaxf(v[0], v[1]), fmaxf(v[2], v[3]));
    __shared__ float red[128];
    red[tid] = mx; __syncthreads();
    for (int o = 64; o > 0; o >>= 1) {
        if (tid < o) red[tid] = fmaxf(red[tid], red[tid + o]);
        __syncthreads();
    }
    mx = red[0]; __syncthreads();
    float e[4]; float ssum = 0.f;
#pragma unroll
    for (int i = 0; i < 4; i++) { e[i] = __expf(v[i] - mx); ssum += e[i]; }
    red[tid] = ssum; __syncthreads();
    for (int o = 64; o > 0; o >>= 1) {
        if (tid < o) red[tid] += red[tid + o];
        __syncthreads();
    }
    float inv = 1.f / red[0];
#pragma unroll
    for (int i = 0; i < 4; i++) out[(size_t)(tid + 128 * i) * SEQ + m] = e[i] * inv;
}

// ---------------- launch ----------------
extern "C" void kernel_launch(void* const* d_in, const int* in_sizes, int n_in,
                              void* d_out, int out_size) {
    const int*   wi  = (const int*)d_in[0];
    const int*   pi  = (const int*)d_in[1];
    const float* we  = (const float*)d_in[2];
    const float* pe  = (const float*)d_in[3];
    const float* wih0f = (const float*)d_in[4];
    const float* whh0f = (const float*)d_in[5];
    const float* b0f   = (const float*)d_in[6];
    const float* wih0b = (const float*)d_in[7];
    const float* whh0b = (const float*)d_in[8];
    const float* b0b   = (const float*)d_in[9];
    const float* wih1f = (const float*)d_in[10];
    const float* whh1f = (const float*)d_in[11];
    const float* b1f   = (const float*)d_in[12];
    const float* wih1b = (const float*)d_in[13];
    const float* whh1b = (const float*)d_in[14];
    const float* b1b   = (const float*)d_in[15];
    const float* W1    = (const float*)d_in[16];
    const float* b1    = (const float*)d_in[17];
    const float* W2    = (const float*)d_in[18];
    const float* b2    = (const float*)d_in[19];
    float* out = (float*)d_out;

    float *p_x0, *p_xw0, *p_xw1, *p_h0, *p_h1, *p_sh, *p_sm;
    cudaGetSymbolAddress((void**)&p_x0, g_x0);
    cudaGetSymbolAddress((void**)&p_xw0, g_xw0);
    cudaGetSymbolAddress((void**)&p_xw1, g_xw1);
    cudaGetSymbolAddress((void**)&p_h0, g_h0);
    cudaGetSymbolAddress((void**)&p_h1, g_h1);
    cudaGetSymbolAddress((void**)&p_sh, g_sh);
    cudaGetSymbolAddress((void**)&p_sm, g_sm);

    // 1. embeddings
    embed_kernel<<<SEQ, 256>>>(wi, pi, we, pe);

    // 2. layer0 input GEMMs
    {
        dim3 grid(GATES / 64, SEQ / 64);
        gemm_nt<<<grid, 256>>>(p_x0, IN0, wih0f, IN0, b0f, p_xw0, GATES, SEQ, GATES, IN0);
        gemm_nt<<<grid, 256>>>(p_x0, IN0, wih0b, IN0, b0b, p_xw1, GATES, SEQ, GATES, IN0);
    }

    // 3. layer0 recurrence
    lstm_layer<<<2 * RCTAS, 256>>>(whh0f, whh0b, p_xw0, p_xw1, p_h0);

    // 4. layer1 input GEMMs
    {
        dim3 grid(GATES / 64, SEQ / 64);
        gemm_nt<<<grid, 256>>>(p_h0, IN1, wih1f, IN1, b1f, p_xw0, GATES, SEQ, GATES, IN1);
        gemm_nt<<<grid, 256>>>(p_h0, IN1, wih1b, IN1, b1b, p_xw1, GATES, SEQ, GATES, IN1);
    }

    // 5. layer1 recurrence
    lstm_layer<<<2 * RCTAS, 256>>>(whh1f, whh1b, p_xw0, p_xw1, p_h1);

    // 6. MLP projections (W1 is [100, 2048] -> ldb = PAIRD)
    {
        dim3 grid((MLPH + 63) / 64, SEQ / 64);
        gemm_nt<<<grid, 256>>>(p_h1, 2 * HID, W1, PAIRD, nullptr, p_sh, MLPH, SEQ, MLPH, 2 * HID);
        gemm_nt<<<grid, 256>>>(p_h1, 2 * HID, W1 + 1024, PAIRD, nullptr, p_sm, MLPH, SEQ, MLPH, 2 * HID);
    }

    // 7. pairwise scores
    {
        dim3 grid(SEQ / 32, SEQ / 32);
        pair_score<<<grid, 256>>>(b1, W2, b2);
    }

    // 8. softmax over heads (axis 0)
    softmax0<<<SEQ, 128>>>(out);
}

// round 6
// speedup vs baseline: 2.1659x; 1.5664x over previous
#include <cuda_runtime.h>
#include <math.h>
#include <stdint.h>

#define SEQ   512
#define HID   512
#define IN0   1088
#define IN1   1024
#define GATES 2048
#define MLPH  100
#define PAIRD 2048
#define RCTAS 64   // CTAs per LSTM direction

// ---------------- device scratch (no allocations allowed) ----------------
__device__ float g_x0[SEQ * IN0];
__device__ float g_xw0[SEQ * GATES];
__device__ float g_xw1[SEQ * GATES];
__device__ float g_h0[SEQ * 2 * HID];
__device__ float g_h1[SEQ * 2 * HID];
__device__ float g_sh[SEQ * MLPH];
__device__ float g_sm[SEQ * MLPH];
__device__ float g_scores[SEQ * SEQ];
__device__ __align__(128) unsigned g_cnt0[32];   // fwd counter (own 128B line)
__device__ __align__(128) unsigned g_cnt1[32];   // bwd counter (own 128B line)

// ---------------- helpers ----------------
__device__ __forceinline__ unsigned ld_acq(const unsigned* p) {
    unsigned v;
    asm volatile("ld.acquire.gpu.u32 %0, [%1];" : "=r"(v) : "l"(p) : "memory");
    return v;
}
__device__ __forceinline__ void red_release_add(unsigned* p, unsigned v) {
    asm volatile("red.release.gpu.global.add.u32 [%0], %1;" :: "l"(p), "r"(v) : "memory");
}
__device__ __forceinline__ float tanhap(float x) {             // HW tanh
    float y;
    asm("tanh.approx.f32 %0, %1;" : "=f"(y) : "f"(x));
    return y;
}
__device__ __forceinline__ float sigap(float x) {              // sigmoid via HW tanh
    return fmaf(0.5f, tanhap(0.5f * x), 0.5f);
}

// ---------------- embeddings ----------------
__global__ void embed_kernel(const int* __restrict__ wi, const int* __restrict__ pi,
                             const float* __restrict__ we, const float* __restrict__ pe) {
    int t = blockIdx.x;
    int w = wi[t], p = pi[t];
    const float* wr = we + (size_t)w * 1024;
    const float* pr = pe + (size_t)p * 64;
    float* out = g_x0 + (size_t)t * IN0;
    for (int i = threadIdx.x; i < 1024; i += blockDim.x) out[i] = wr[i];
    for (int i = threadIdx.x; i < 64; i += blockDim.x) out[1024 + i] = pr[i];
}

// ---------------- generic tiled GEMM: C[M,N] = A[M,K] * B[N,K]^T (+bias) ----------------
__global__ void gemm_nt(const float* __restrict__ A, int lda,
                        const float* __restrict__ B, int ldb,
                        const float* __restrict__ bias,
                        float* __restrict__ C, int ldc,
                        int M, int N, int K) {
    __shared__ __align__(16) float As[16][68];
    __shared__ __align__(16) float Bs[16][68];
    int bm = blockIdx.y * 64, bn = blockIdx.x * 64;
    int tid = threadIdx.x;
    int tx = tid & 15, ty = tid >> 4;
    int lr = tid >> 2;
    int lk = (tid & 3) * 4;

    float acc[4][4];
#pragma unroll
    for (int i = 0; i < 4; i++)
#pragma unroll
        for (int j = 0; j < 4; j++) acc[i][j] = 0.f;

    for (int k0 = 0; k0 < K; k0 += 16) {
        {
            int row = bm + lr;
            float4 v = make_float4(0.f, 0.f, 0.f, 0.f);
            if (row < M) v = *(const float4*)(A + (size_t)row * lda + k0 + lk);
            As[lk + 0][lr] = v.x; As[lk + 1][lr] = v.y; As[lk + 2][lr] = v.z; As[lk + 3][lr] = v.w;
            int rowb = bn + lr;
            float4 u = make_float4(0.f, 0.f, 0.f, 0.f);
            if (rowb < N) u = *(const float4*)(B + (size_t)rowb * ldb + k0 + lk);
            Bs[lk + 0][lr] = u.x; Bs[lk + 1][lr] = u.y; Bs[lk + 2][lr] = u.z; Bs[lk + 3][lr] = u.w;
        }
        __syncthreads();
#pragma unroll
        for (int k = 0; k < 16; k++) {
            float4 a4 = *(const float4*)&As[k][ty * 4];
            float4 b4 = *(const float4*)&Bs[k][tx * 4];
            float a[4] = {a4.x, a4.y, a4.z, a4.w};
            float b[4] = {b4.x, b4.y, b4.z, b4.w};
#pragma unroll
            for (int i = 0; i < 4; i++)
#pragma unroll
                for (int j = 0; j < 4; j++) acc[i][j] = fmaf(a[i], b[j], acc[i][j]);
        }
        __syncthreads();
    }
#pragma unroll
    for (int i = 0; i < 4; i++) {
        int r = bm + ty * 4 + i;
        if (r >= M) continue;
#pragma unroll
        for (int j = 0; j < 4; j++) {
            int c = bn + tx * 4 + j;
            if (c < N) C[(size_t)r * ldc + c] = acc[i][j] + (bias ? bias[c] : 0.f);
        }
    }
}

// ---------------- LSTM recurrence: register weights + flat release-counter barrier ------
// grid = 128 CTAs (64 fwd, 64 bwd), 256 threads. CTA owns 8 h-indices (32 gate rows).
// Thread (row=tid&31, ck=tid>>5) holds 64 weights in registers.
__global__ void __launch_bounds__(256, 1)
lstm_layer(const float* __restrict__ whh_f, const float* __restrict__ whh_b,
           const float* __restrict__ xw_f, const float* __restrict__ xw_b,
           float* __restrict__ hout) {
    __shared__ float sh[512];
    __shared__ float zp[32 * 9];
    __shared__ float sact[32];

    int dir = blockIdx.x >> 6;
    int j = blockIdx.x & 63;
    int hbase = j * 8;
    const float* W = dir ? whh_b : whh_f;
    const float* xw = dir ? xw_b : xw_f;
    int tid = threadIdx.x;
    unsigned* cnt = dir ? &g_cnt1[0] : &g_cnt0[0];

    int row = tid & 31;            // gate row within CTA (0..31)
    int ck = tid >> 5;             // K chunk (0..7)
    const int base = ck * 64;

    // weights into registers: global gate row (row>>3)*512 + hbase + (row&7), cols [base,base+64)
    float w[64];
    {
        const float* src = W + (size_t)((row >> 3) * 512 + hbase + (row & 7)) * 512 + base;
#pragma unroll
        for (int i = 0; i < 64; i += 4) {
            float4 v = *(const float4*)(src + i);
            w[i] = v.x; w[i + 1] = v.y; w[i + 2] = v.z; w[i + 3] = v.w;
        }
    }

    float c_state = 0.f;           // owned by threads 0..7

    for (int t = 0; t < 512; t++) {
        int pos = dir ? (511 - t) : t;

        // prefetch gate inputs (independent of h) — overlaps the spin below
        float xg = 0.f;
        if (tid < 32) {
            const float* xr = xw + (size_t)pos * GATES + (tid >> 3) * 512 + hbase + (tid & 7);
            xg = __ldg(xr);
        }

        // warps 0-1: observe previous step's completion, then gather h into smem
        if (t == 0) {
            if (tid < 64) {
                float* d = sh + (tid << 3);
                *(float4*)d = make_float4(0.f, 0.f, 0.f, 0.f);
                *(float4*)(d + 4) = make_float4(0.f, 0.f, 0.f, 0.f);
            }
        } else if (tid < 64) {
            unsigned target = (unsigned)t * RCTAS;
            while (ld_acq(cnt) < target) { }
            int ppos = dir ? (pos + 1) : (t - 1);
            const float* hp = hout + (size_t)ppos * 1024 + (dir << 9) + (tid << 3);
            float4 a = __ldcg((const float4*)hp);
            float4 b = __ldcg((const float4*)(hp + 4));
            float* d = sh + (tid << 3);
            *(float4*)d = a;
            *(float4*)(d + 4) = b;
        }
        __syncthreads();   // (B) sh ready

        // matvec partial: register weights x broadcast smem h
        {
            const float* hv = sh + base;
            float a0 = 0.f, a1 = 0.f, a2 = 0.f, a3 = 0.f;
#pragma unroll
            for (int i = 0; i < 64; i += 4) {
                float4 h4 = *(const float4*)(hv + i);
                a0 = fmaf(w[i + 0], h4.x, a0);
                a1 = fmaf(w[i + 1], h4.y, a1);
                a2 = fmaf(w[i + 2], h4.z, a2);
                a3 = fmaf(w[i + 3], h4.w, a3);
            }
            zp[row * 9 + ck] = (a0 + a1) + (a2 + a3);
        }
        __syncthreads();   // (C) zp ready

        // warp 0: 32 threads do per-gate-row sum + activation; 8 owners update state
        if (tid < 32) {
            const float* zr = zp + tid * 9;
            float z = xg;
#pragma unroll
            for (int c = 0; c < 8; c++) z += zr[c];
            sact[tid] = ((tid >> 3) == 2) ? tanhap(z) : sigap(z);
        }
        __syncwarp();
        if (tid < 8) {
            float gi = sact[tid];
            float gf = sact[8 + tid];
            float gg = sact[16 + tid];
            float go_ = sact[24 + tid];
            c_state = gf * c_state + gi * gg;
            float h = go_ * tanhap(c_state);
            __stcg(hout + (size_t)pos * 1024 + (dir << 9) + hbase + tid, h);
        }
        __syncwarp();
        if (tid == 0) {
            red_release_add(cnt, 1u);   // release orders the h stores (warp-sync edge above)
        }
    }

    // exit protocol: CTA j==0 per direction waits for full count, resets for replay
    if (tid == 0 && j == 0) {
        while (ld_acq(cnt) < 512u * RCTAS) { }
        atomicExch(cnt, 0u);
    }
}

// ---------------- pairwise MLP edge scores ----------------
__global__ void pair_score(const float* __restrict__ b1, const float* __restrict__ W2,
                           const float* __restrict__ b2) {
    __shared__ float Sh[32][101];
    __shared__ float Sm[32][101];
    __shared__ float sb1[MLPH], sw2[MLPH];
    int bh = blockIdx.y * 32, bm = blockIdx.x * 32;
    int tid = threadIdx.x;
    for (int i = tid; i < 32 * MLPH; i += 256) {
        int r = i / MLPH, c = i % MLPH;
        Sh[r][c] = g_sh[(size_t)(bh + r) * MLPH + c];
        Sm[r][c] = g_sm[(size_t)(bm + r) * MLPH + c];
    }
    if (tid < MLPH) { sb1[tid] = b1[tid]; sw2[tid] = W2[tid]; }
    __syncthreads();

    int tx = tid & 15, ty = tid >> 4;
    int h0 = ty * 2, m0 = tx * 2;
    float acc00 = 0.f, acc01 = 0.f, acc10 = 0.f, acc11 = 0.f;
    for (int jx = 0; jx < MLPH; jx++) {
        float w = sw2[jx], bb = sb1[jx];
        float a0 = Sh[h0][jx] + bb;
        float a1 = Sh[h0 + 1][jx] + bb;
        float c0 = Sm[m0][jx];
        float c1 = Sm[m0 + 1][jx];
        acc00 = fmaf(tanhap(a0 + c0), w, acc00);
        acc01 = fmaf(tanhap(a0 + c1), w, acc01);
        acc10 = fmaf(tanhap(a1 + c0), w, acc10);
        acc11 = fmaf(tanhap(a1 + c1), w, acc11);
    }
    float b2v = __ldg(b2);
    g_scores[(size_t)(bh + h0) * SEQ + bm + m0]         = acc00 + b2v;
    g_scores[(size_t)(bh + h0) * SEQ + bm + m0 + 1]     = acc01 + b2v;
    g_scores[(size_t)(bh + h0 + 1) * SEQ + bm + m0]     = acc10 + b2v;
    g_scores[(size_t)(bh + h0 + 1) * SEQ + bm + m0 + 1] = acc11 + b2v;
}

// ---------------- softmax over axis 0 ----------------
__global__ void softmax0(float* __restrict__ out) {
    int m = blockIdx.x;
    int tid = threadIdx.x;  // 128
    float v[4];
#pragma unroll
    for (int i = 0; i < 4; i++) v[i] = g_scores[(size_t)(tid + 128 * i) * SEQ + m];
    float mx = fmaxf(fmaxf(v[0], v[1]), fmaxf(v[2], v[3]));
    __shared__ float red[128];
    red[tid] = mx; __syncthreads();
    for (int o = 64; o > 0; o >>= 1) {
        if (tid < o) red[tid] = fmaxf(red[tid], red[tid + o]);
        __syncthreads();
    }
    mx = red[0]; __syncthreads();
    float e[4]; float ssum = 0.f;
#pragma unroll
    for (int i = 0; i < 4; i++) { e[i] = __expf(v[i] - mx); ssum += e[i]; }
    red[tid] = ssum; __syncthreads();
    for (int o = 64; o > 0; o >>= 1) {
        if (tid < o) red[tid] += red[tid + o];
        __syncthreads();
    }
    float inv = 1.f / red[0];
#pragma unroll
    for (int i = 0; i < 4; i++) out[(size_t)(tid + 128 * i) * SEQ + m] = e[i] * inv;
}

// ---------------- launch ----------------
extern "C" void kernel_launch(void* const* d_in, const int* in_sizes, int n_in,
                              void* d_out, int out_size) {
    const int*   wi  = (const int*)d_in[0];
    const int*   pi  = (const int*)d_in[1];
    const float* we  = (const float*)d_in[2];
    const float* pe  = (const float*)d_in[3];
    const float* wih0f = (const float*)d_in[4];
    const float* whh0f = (const float*)d_in[5];
    const float* b0f   = (const float*)d_in[6];
    const float* wih0b = (const float*)d_in[7];
    const float* whh0b = (const float*)d_in[8];
    const float* b0b   = (const float*)d_in[9];
    const float* wih1f = (const float*)d_in[10];
    const float* whh1f = (const float*)d_in[11];
    const float* b1f   = (const float*)d_in[12];
    const float* wih1b = (const float*)d_in[13];
    const float* whh1b = (const float*)d_in[14];
    const float* b1b   = (const float*)d_in[15];
    const float* W1    = (const float*)d_in[16];
    const float* b1    = (const float*)d_in[17];
    const float* W2    = (const float*)d_in[18];
    const float* b2    = (const float*)d_in[19];
    float* out = (float*)d_out;

    float *p_x0, *p_xw0, *p_xw1, *p_h0, *p_h1, *p_sh, *p_sm;
    cudaGetSymbolAddress((void**)&p_x0, g_x0);
    cudaGetSymbolAddress((void**)&p_xw0, g_xw0);
    cudaGetSymbolAddress((void**)&p_xw1, g_xw1);
    cudaGetSymbolAddress((void**)&p_h0, g_h0);
    cudaGetSymbolAddress((void**)&p_h1, g_h1);
    cudaGetSymbolAddress((void**)&p_sh, g_sh);
    cudaGetSymbolAddress((void**)&p_sm, g_sm);

    // 1. embeddings
    embed_kernel<<<SEQ, 256>>>(wi, pi, we, pe);

    // 2. layer0 input GEMMs
    {
        dim3 grid(GATES / 64, SEQ / 64);
        gemm_nt<<<grid, 256>>>(p_x0, IN0, wih0f, IN0, b0f, p_xw0, GATES, SEQ, GATES, IN0);
        gemm_nt<<<grid, 256>>>(p_x0, IN0, wih0b, IN0, b0b, p_xw1, GATES, SEQ, GATES, IN0);
    }

    // 3. layer0 recurrence
    lstm_layer<<<2 * RCTAS, 256>>>(whh0f, whh0b, p_xw0, p_xw1, p_h0);

    // 4. layer1 input GEMMs
    {
        dim3 grid(GATES / 64, SEQ / 64);
        gemm_nt<<<grid, 256>>>(p_h0, IN1, wih1f, IN1, b1f, p_xw0, GATES, SEQ, GATES, IN1);
        gemm_nt<<<grid, 256>>>(p_h0, IN1, wih1b, IN1, b1b, p_xw1, GATES, SEQ, GATES, IN1);
    }

    // 5. layer1 recurrence
    lstm_layer<<<2 * RCTAS, 256>>>(whh1f, whh1b, p_xw0, p_xw1, p_h1);

    // 6. MLP projections (W1 is [100, 2048] -> ldb = PAIRD)
    {
        dim3 grid((MLPH + 63) / 64, SEQ / 64);
        gemm_nt<<<grid, 256>>>(p_h1, 2 * HID, W1, PAIRD, nullptr, p_sh, MLPH, SEQ, MLPH, 2 * HID);
        gemm_nt<<<grid, 256>>>(p_h1, 2 * HID, W1 + 1024, PAIRD, nullptr, p_sm, MLPH, SEQ, MLPH, 2 * HID);
    }

    // 7. pairwise scores
    {
        dim3 grid(SEQ / 32, SEQ / 32);
        pair_score<<<grid, 256>>>(b1, W2, b2);
    }

    // 8. softmax over heads (axis 0)
    softmax0<<<SEQ, 128>>>(out);
}

// round 7
// speedup vs baseline: 3.1657x; 1.4616x over previous
#include <cuda_runtime.h>
#include <math.h>
#include <stdint.h>

#define SEQ   512
#define HID   512
#define IN0   1088
#define IN1   1024
#define GATES 2048
#define MLPH  100
#define PAIRD 2048
#define RCTAS 64   // CTAs per LSTM direction
#define WIN   1.5f

// ---------------- device scratch (no allocations allowed) ----------------
__device__ float g_x0[SEQ * IN0];
__device__ float g_xw0[SEQ * GATES];
__device__ float g_xw1[SEQ * GATES];
__device__ float g_h0[SEQ * 2 * HID];
__device__ float g_h1[SEQ * 2 * HID];
__device__ float g_sh[SEQ * MLPH];
__device__ float g_sm[SEQ * MLPH];
__device__ float g_scores[SEQ * SEQ];
// self-validating h exchange: [dir][buffer=t&1][granule 0..255] (8B = 2 h values)
__device__ __align__(128) unsigned long long g_hx[2][2][256];
__device__ __align__(128) unsigned g_cnt[2][32];    // one-time start barrier
__device__ __align__(128) unsigned g_exit[2][32];   // exit/reset barrier

// ---------------- helpers ----------------
__device__ __forceinline__ unsigned ld_acq(const unsigned* p) {
    unsigned v;
    asm volatile("ld.acquire.gpu.u32 %0, [%1];" : "=r"(v) : "l"(p) : "memory");
    return v;
}
__device__ __forceinline__ unsigned long long ld_rlx64(const unsigned long long* p) {
    unsigned long long v;
    asm volatile("ld.relaxed.gpu.global.b64 %0, [%1];" : "=l"(v) : "l"(p) : "memory");
    return v;
}
__device__ __forceinline__ void st_rlx64(unsigned long long* p, unsigned long long v) {
    asm volatile("st.relaxed.gpu.global.b64 [%0], %1;" :: "l"(p), "l"(v) : "memory");
}
__device__ __forceinline__ float tanhap(float x) {             // HW tanh
    float y;
    asm("tanh.approx.f32 %0, %1;" : "=f"(y) : "f"(x));
    return y;
}
__device__ __forceinline__ float sigap(float x) {              // sigmoid via HW tanh
    return fmaf(0.5f, tanhap(0.5f * x), 0.5f);
}

// ---------------- embeddings ----------------
__global__ void embed_kernel(const int* __restrict__ wi, const int* __restrict__ pi,
                             const float* __restrict__ we, const float* __restrict__ pe) {
    int t = blockIdx.x;
    int w = wi[t], p = pi[t];
    const float* wr = we + (size_t)w * 1024;
    const float* pr = pe + (size_t)p * 64;
    float* out = g_x0 + (size_t)t * IN0;
    for (int i = threadIdx.x; i < 1024; i += blockDim.x) out[i] = wr[i];
    for (int i = threadIdx.x; i < 64; i += blockDim.x) out[1024 + i] = pr[i];
}

// ---------------- generic tiled GEMM: C[M,N] = A[M,K] * B[N,K]^T (+bias) ----------------
__global__ void gemm_nt(const float* __restrict__ A, int lda,
                        const float* __restrict__ B, int ldb,
                        const float* __restrict__ bias,
                        float* __restrict__ C, int ldc,
                        int M, int N, int K) {
    __shared__ __align__(16) float As[16][68];
    __shared__ __align__(16) float Bs[16][68];
    int bm = blockIdx.y * 64, bn = blockIdx.x * 64;
    int tid = threadIdx.x;
    int tx = tid & 15, ty = tid >> 4;
    int lr = tid >> 2;
    int lk = (tid & 3) * 4;

    float acc[4][4];
#pragma unroll
    for (int i = 0; i < 4; i++)
#pragma unroll
        for (int j = 0; j < 4; j++) acc[i][j] = 0.f;

    for (int k0 = 0; k0 < K; k0 += 16) {
        {
            int row = bm + lr;
            float4 v = make_float4(0.f, 0.f, 0.f, 0.f);
            if (row < M) v = *(const float4*)(A + (size_t)row * lda + k0 + lk);
            As[lk + 0][lr] = v.x; As[lk + 1][lr] = v.y; As[lk + 2][lr] = v.z; As[lk + 3][lr] = v.w;
            int rowb = bn + lr;
            float4 u = make_float4(0.f, 0.f, 0.f, 0.f);
            if (rowb < N) u = *(const float4*)(B + (size_t)rowb * ldb + k0 + lk);
            Bs[lk + 0][lr] = u.x; Bs[lk + 1][lr] = u.y; Bs[lk + 2][lr] = u.z; Bs[lk + 3][lr] = u.w;
        }
        __syncthreads();
#pragma unroll
        for (int k = 0; k < 16; k++) {
            float4 a4 = *(const float4*)&As[k][ty * 4];
            float4 b4 = *(const float4*)&Bs[k][tx * 4];
            float a[4] = {a4.x, a4.y, a4.z, a4.w};
            float b[4] = {b4.x, b4.y, b4.z, b4.w};
#pragma unroll
            for (int i = 0; i < 4; i++)
#pragma unroll
                for (int j = 0; j < 4; j++) acc[i][j] = fmaf(a[i], b[j], acc[i][j]);
        }
        __syncthreads();
    }
#pragma unroll
    for (int i = 0; i < 4; i++) {
        int r = bm + ty * 4 + i;
        if (r >= M) continue;
#pragma unroll
        for (int j = 0; j < 4; j++) {
            int c = bn + tx * 4 + j;
            if (c < N) C[(size_t)r * ldc + c] = acc[i][j] + (bias ? bias[c] : 0.f);
        }
    }
}

// ---------------- LSTM recurrence: register weights + self-validating h exchange --------
// grid = 128 CTAs (64 fwd, 64 bwd), 256 threads. CTA owns 8 h-indices (32 gate rows).
// h published as v = h + 4*(t mod 7), double-buffered by t&1; value IS the sync.
__global__ void __launch_bounds__(256, 1)
lstm_layer(const float* __restrict__ whh_f, const float* __restrict__ whh_b,
           const float* __restrict__ xw_f, const float* __restrict__ xw_b,
           float* __restrict__ hout) {
    __shared__ float sh[512];
    __shared__ float zp[32 * 9];
    __shared__ float sact[32];

    int dir = blockIdx.x >> 6;
    int j = blockIdx.x & 63;
    int hbase = j * 8;
    const float* W = dir ? whh_b : whh_f;
    const float* xw = dir ? xw_b : xw_f;
    int tid = threadIdx.x;

    int row = tid & 31;            // gate row within CTA (0..31)
    int ck = tid >> 5;             // K chunk (0..7)
    const int base = ck * 64;

    // weights into registers
    float w[64];
    {
        const float* src = W + (size_t)((row >> 3) * 512 + hbase + (row & 7)) * 512 + base;
#pragma unroll
        for (int i = 0; i < 64; i += 4) {
            float4 v = *(const float4*)(src + i);
            w[i] = v.x; w[i + 1] = v.y; w[i + 2] = v.z; w[i + 3] = v.w;
        }
    }

    // one-time: poison own hx granules, then grid start-barrier (per direction)
    if (tid == 0) {
        unsigned long long poison =
            ((unsigned long long)__float_as_uint(1e30f) << 32) | __float_as_uint(1e30f);
#pragma unroll
        for (int b = 0; b < 2; b++)
#pragma unroll
            for (int q = 0; q < 4; q++)
                st_rlx64(&g_hx[dir][b][j * 4 + q], poison);
        __threadfence();
        atomicAdd(&g_cnt[dir][0], 1u);
        while (ld_acq(&g_cnt[dir][0]) < (unsigned)RCTAS) { }
    }
    __syncthreads();

    float c_state = 0.f;           // owned by threads 0..7
    int kp = 0, kc = 0;            // t mod 7 (producer), (t-1) mod 7 (consumer)

    for (int t = 0; t < 512; t++) {
        int pos = dir ? (511 - t) : t;
        float coffp = 4.0f * (float)kp;
        float coffc = 4.0f * (float)kc;

        // prefetch gate inputs (independent of h) — overlaps the poll below
        float xg = 0.f;
        if (tid < 32) {
            const float* xr = xw + (size_t)pos * GATES + (tid >> 3) * 512 + hbase + (tid & 7);
            xg = __ldg(xr);
        }

        // gather h_prev: every thread polls ONE self-validating 8B granule
        if (t == 0) {
            ((float2*)sh)[tid] = make_float2(0.f, 0.f);
        } else {
            const unsigned long long* src = &g_hx[dir][(t - 1) & 1][tid];
            float lo, hi;
            for (;;) {
                unsigned long long v = ld_rlx64(src);
                lo = __uint_as_float((unsigned)v);
                hi = __uint_as_float((unsigned)(v >> 32));
                if (fabsf(lo - coffc) <= WIN && fabsf(hi - coffc) <= WIN) break;
            }
            ((float2*)sh)[tid] = make_float2(lo - coffc, hi - coffc);
        }
        __syncthreads();   // sh ready

        // matvec partial: register weights x broadcast smem h
        {
            const float* hv = sh + base;
            float a0 = 0.f, a1 = 0.f, a2 = 0.f, a3 = 0.f;
#pragma unroll
            for (int i = 0; i < 64; i += 4) {
                float4 h4 = *(const float4*)(hv + i);
                a0 = fmaf(w[i + 0], h4.x, a0);
                a1 = fmaf(w[i + 1], h4.y, a1);
                a2 = fmaf(w[i + 2], h4.z, a2);
                a3 = fmaf(w[i + 3], h4.w, a3);
            }
            zp[row * 9 + ck] = (a0 + a1) + (a2 + a3);
        }
        __syncthreads();   // zp ready

        // warp 0: gate-row sums + activations; 8 owners update state + publish
        if (tid < 32) {
            const float* zr = zp + tid * 9;
            float z = xg;
#pragma unroll
            for (int c = 0; c < 8; c++) z += zr[c];
            sact[tid] = ((tid >> 3) == 2) ? tanhap(z) : sigap(z);
        }
        __syncwarp();
        if (tid < 8) {
            float gi = sact[tid];
            float gf = sact[8 + tid];
            float gg = sact[16 + tid];
            float go_ = sact[24 + tid];
            c_state = gf * c_state + gi * gg;
            float h = go_ * tanhap(c_state);
            __stcg(hout + (size_t)pos * 1024 + (dir << 9) + hbase + tid, h);
            // publish: v = h + 4*(t%7), packed 2-per-b64, fire-and-forget
            float vv = h + coffp;
            float partner = __shfl_xor_sync(0x000000FFu, vv, 1);
            if ((tid & 1) == 0) {
                unsigned long long pk =
                    ((unsigned long long)__float_as_uint(partner) << 32) | __float_as_uint(vv);
                st_rlx64(&g_hx[dir][t & 1][j * 4 + (tid >> 1)], pk);
            }
        }
        kc = kp;
        kp = (kp == 6) ? 0 : kp + 1;
    }

    // exit/reset: make counters zero for the next launch / graph replay
    __syncthreads();
    if (tid == 0) {
        __threadfence();
        atomicAdd(&g_exit[dir][0], 1u);
        if (j == 0) {
            while (ld_acq(&g_exit[dir][0]) < (unsigned)RCTAS) { }
            g_cnt[dir][0] = 0u;
            __threadfence();
            atomicExch(&g_exit[dir][0], 0u);
        }
    }
}

// ---------------- pairwise MLP edge scores ----------------
__global__ void pair_score(const float* __restrict__ b1, const float* __restrict__ W2,
                           const float* __restrict__ b2) {
    __shared__ float Sh[32][101];
    __shared__ float Sm[32][101];
    __shared__ float sb1[MLPH], sw2[MLPH];
    int bh = blockIdx.y * 32, bm = blockIdx.x * 32;
    int tid = threadIdx.x;
    for (int i = tid; i < 32 * MLPH; i += 256) {
        int r = i / MLPH, c = i % MLPH;
        Sh[r][c] = g_sh[(size_t)(bh + r) * MLPH + c];
        Sm[r][c] = g_sm[(size_t)(bm + r) * MLPH + c];
    }
    if (tid < MLPH) { sb1[tid] = b1[tid]; sw2[tid] = W2[tid]; }
    __syncthreads();

    int tx = tid & 15, ty = tid >> 4;
    int h0 = ty * 2, m0 = tx * 2;
    float acc00 = 0.f, acc01 = 0.f, acc10 = 0.f, acc11 = 0.f;
    for (int jx = 0; jx < MLPH; jx++) {
        float w = sw2[jx], bb = sb1[jx];
        float a0 = Sh[h0][jx] + bb;
        float a1 = Sh[h0 + 1][jx] + bb;
        float c0 = Sm[m0][jx];
        float c1 = Sm[m0 + 1][jx];
        acc00 = fmaf(tanhap(a0 + c0), w, acc00);
        acc01 = fmaf(tanhap(a0 + c1), w, acc01);
        acc10 = fmaf(tanhap(a1 + c0), w, acc10);
        acc11 = fmaf(tanhap(a1 + c1), w, acc11);
    }
    float b2v = __ldg(b2);
    g_scores[(size_t)(bh + h0) * SEQ + bm + m0]         = acc00 + b2v;
    g_scores[(size_t)(bh + h0) * SEQ + bm + m0 + 1]     = acc01 + b2v;
    g_scores[(size_t)(bh + h0 + 1) * SEQ + bm + m0]     = acc10 + b2v;
    g_scores[(size_t)(bh + h0 + 1) * SEQ + bm + m0 + 1] = acc11 + b2v;
}

// ---------------- softmax over axis 0 ----------------
__global__ void softmax0(float* __restrict__ out) {
    int m = blockIdx.x;
    int tid = threadIdx.x;  // 128
    float v[4];
#pragma unroll
    for (int i = 0; i < 4; i++) v[i] = g_scores[(size_t)(tid + 128 * i) * SEQ + m];
    float mx = fmaxf(fmaxf(v[0], v[1]), fmaxf(v[2], v[3]));
    __shared__ float red[128];
    red[tid] = mx; __syncthreads();
    for (int o = 64; o > 0; o >>= 1) {
        if (tid < o) red[tid] = fmaxf(red[tid], red[tid + o]);
        __syncthreads();
    }
    mx = red[0]; __syncthreads();
    float e[4]; float ssum = 0.f;
#pragma unroll
    for (int i = 0; i < 4; i++) { e[i] = __expf(v[i] - mx); ssum += e[i]; }
    red[tid] = ssum; __syncthreads();
    for (int o = 64; o > 0; o >>= 1) {
        if (tid < o) red[tid] += red[tid + o];
        __syncthreads();
    }
    float inv = 1.f / red[0];
#pragma unroll
    for (int i = 0; i < 4; i++) out[(size_t)(tid + 128 * i) * SEQ + m] = e[i] * inv;
}

// ---------------- launch ----------------
extern "C" void kernel_launch(void* const* d_in, const int* in_sizes, int n_in,
                              void* d_out, int out_size) {
    const int*   wi  = (const int*)d_in[0];
    const int*   pi  = (const int*)d_in[1];
    const float* we  = (const float*)d_in[2];
    const float* pe  = (const float*)d_in[3];
    const float* wih0f = (const float*)d_in[4];
    const float* whh0f = (const float*)d_in[5];
    const float* b0f   = (const float*)d_in[6];
    const float* wih0b = (const float*)d_in[7];
    const float* whh0b = (const float*)d_in[8];
    const float* b0b   = (const float*)d_in[9];
    const float* wih1f = (const float*)d_in[10];
    const float* whh1f = (const float*)d_in[11];
    const float* b1f   = (const float*)d_in[12];
    const float* wih1b = (const float*)d_in[13];
    const float* whh1b = (const float*)d_in[14];
    const float* b1b   = (const float*)d_in[15];
    const float* W1    = (const float*)d_in[16];
    const float* b1    = (const float*)d_in[17];
    const float* W2    = (const float*)d_in[18];
    const float* b2    = (const float*)d_in[19];
    float* out = (float*)d_out;

    float *p_x0, *p_xw0, *p_xw1, *p_h0, *p_h1, *p_sh, *p_sm;
    cudaGetSymbolAddress((void**)&p_x0, g_x0);
    cudaGetSymbolAddress((void**)&p_xw0, g_xw0);
    cudaGetSymbolAddress((void**)&p_xw1, g_xw1);
    cudaGetSymbolAddress((void**)&p_h0, g_h0);
    cudaGetSymbolAddress((void**)&p_h1, g_h1);
    cudaGetSymbolAddress((void**)&p_sh, g_sh);
    cudaGetSymbolAddress((void**)&p_sm, g_sm);

    // 1. embeddings
    embed_kernel<<<SEQ, 256>>>(wi, pi, we, pe);

    // 2. layer0 input GEMMs
    {
        dim3 grid(GATES / 64, SEQ / 64);
        gemm_nt<<<grid, 256>>>(p_x0, IN0, wih0f, IN0, b0f, p_xw0, GATES, SEQ, GATES, IN0);
        gemm_nt<<<grid, 256>>>(p_x0, IN0, wih0b, IN0, b0b, p_xw1, GATES, SEQ, GATES, IN0);
    }

    // 3. layer0 recurrence
    lstm_layer<<<2 * RCTAS, 256>>>(whh0f, whh0b, p_xw0, p_xw1, p_h0);

    // 4. layer1 input GEMMs
    {
        dim3 grid(GATES / 64, SEQ / 64);
        gemm_nt<<<grid, 256>>>(p_h0, IN1, wih1f, IN1, b1f, p_xw0, GATES, SEQ, GATES, IN1);
        gemm_nt<<<grid, 256>>>(p_h0, IN1, wih1b, IN1, b1b, p_xw1, GATES, SEQ, GATES, IN1);
    }

    // 5. layer1 recurrence
    lstm_layer<<<2 * RCTAS, 256>>>(whh1f, whh1b, p_xw0, p_xw1, p_h1);

    // 6. MLP projections (W1 is [100, 2048] -> ldb = PAIRD)
    {
        dim3 grid((MLPH + 63) / 64, SEQ / 64);
        gemm_nt<<<grid, 256>>>(p_h1, 2 * HID, W1, PAIRD, nullptr, p_sh, MLPH, SEQ, MLPH, 2 * HID);
        gemm_nt<<<grid, 256>>>(p_h1, 2 * HID, W1 + 1024, PAIRD, nullptr, p_sm, MLPH, SEQ, MLPH, 2 * HID);
    }

    // 7. pairwise scores
    {
        dim3 grid(SEQ / 32, SEQ / 32);
        pair_score<<<grid, 256>>>(b1, W2, b2);
    }

    // 8. softmax over heads (axis 0)
    softmax0<<<SEQ, 128>>>(out);
}